// round 13
// baseline (speedup 1.0000x reference)
#include <cuda_runtime.h>
#include <cstdint>

#define TPB    256
#define NBLK   912       // 152 SMs * 6 resident blocks
#define DEPTH  4         // pipeline stages
#define SLEN   2048      // floats per stage (8 KB; 16B-aligned boundaries)

// ---------------------------------------------------------------------------
// out = sum_i x[i]*c[i] + sum_{i<j} x[i]*x[j]*c2[base(i)+(j-i-1)]
// c2 = c + n, base(i) = i*(2n-1-i)/2  (row-major packed upper triangle).
//
// Coeff stream arrives via TMA bulk copies (cp.async.bulk g->smem, mbarrier
// complete_tx), bypassing the L1tex/LDG miss path entirely. Each block owns a
// contiguous run of 8KB stages; DEPTH-deep pipeline keeps 24KB in flight per
// block (144KB/SM). Consumers walk uniform row-segments: smem LDS + L1-hit
// x LDG + FMA. Single kernel; last-arriving block reduces partials.
// ---------------------------------------------------------------------------

__device__ float        g_parts[NBLK];
__device__ unsigned int g_ctr = 0;

__device__ __forceinline__ float warp_sum(float v) {
    #pragma unroll
    for (int o = 16; o > 0; o >>= 1) v += __shfl_down_sync(0xffffffffu, v, o);
    return v;
}

__device__ __forceinline__ void mbar_init(uint32_t mba, uint32_t count) {
    asm volatile("mbarrier.init.shared.b64 [%0], %1;" :: "r"(mba), "r"(count) : "memory");
}
__device__ __forceinline__ void mbar_expect_tx(uint32_t mba, uint32_t bytes) {
    asm volatile("mbarrier.arrive.expect_tx.shared.b64 _, [%0], %1;"
                 :: "r"(mba), "r"(bytes) : "memory");
}
__device__ __forceinline__ void mbar_wait(uint32_t mba, uint32_t parity) {
    asm volatile(
        "{\n\t"
        ".reg .pred P;\n\t"
        "LAB_WAIT_%=:\n\t"
        "mbarrier.try_wait.parity.shared.b64 P, [%0], %1, 10000000;\n\t"
        "@P bra LAB_DONE_%=;\n\t"
        "bra.uni LAB_WAIT_%=;\n\t"
        "LAB_DONE_%=:\n\t"
        "}"
        :: "r"(mba), "r"(parity) : "memory");
}
__device__ __forceinline__ void tma_1d(uint32_t dst, const float* src,
                                       uint32_t bytes, uint32_t mba) {
    asm volatile(
        "cp.async.bulk.shared::cluster.global.mbarrier::complete_tx::bytes "
        "[%0], [%1], %2, [%3];"
        :: "r"(dst), "l"(src), "r"(bytes), "r"(mba) : "memory");
}

__global__ __launch_bounds__(TPB, 6)
void ham_kernel(const float* __restrict__ x,
                const float* __restrict__ c,
                float* __restrict__ out,
                int n) {
    __shared__ __align__(16) float buf[DEPTH][SLEN];   // 32 KB
    __shared__ __align__(8)  unsigned long long mbar[DEPTH];
    __shared__ float wsum[TPB / 32];
    __shared__ int lastflag;

    const int t = threadIdx.x;
    const int b = blockIdx.x;
    const int G = gridDim.x;
    const float* c2 = c + n;

    const int total = (n * (n - 1)) >> 1;     // 33,550,336
    const int nch   = total / SLEN;           // 16,382 exactly for n=8192

    uint32_t mba[DEPTH];
    #pragma unroll
    for (int d = 0; d < DEPTH; ++d)
        mba[d] = (uint32_t)__cvta_generic_to_shared(&mbar[d]);

    if (t == 0) {
        #pragma unroll
        for (int d = 0; d < DEPTH; ++d) mbar_init(mba[d], 1);
    }
    __syncthreads();

    const int s0  = (int)(((long long)b       * nch) / G);
    const int s1  = (int)(((long long)(b + 1) * nch) / G);
    const int nst = s1 - s0;

    float sum = 0.0f;

    // degree-1 terms, spread over all blocks
    for (int k = b * TPB + t; k < n; k += G * TPB)
        sum += __ldg(x + k) * __ldg(c + k);

    if (nst > 0) {
        // prologue: fill the pipeline
        if (t == 0) {
            const int pmax = nst < DEPTH ? nst : DEPTH;
            for (int d = 0; d < pmax; ++d) {
                mbar_expect_tx(mba[d], SLEN * 4);
                tma_1d((uint32_t)__cvta_generic_to_shared(&buf[d][0]),
                       c2 + (long long)(s0 + d) * SLEN, SLEN * 4, mba[d]);
            }
        }

        // decode starting row for g0 = s0*SLEN (double seed + exact fixup)
        const int g0 = s0 * SLEN;
        const double nd = 2.0 * (double)n - 1.0;
        int i = (int)((nd - sqrt(nd * nd - 8.0 * (double)g0)) * 0.5);
        if (i < 0) i = 0;
        if (i > n - 2) i = n - 2;
        int rb = (i * (2 * n - 1 - i)) >> 1;
        while (rb > g0) { --i; rb -= (n - 1 - i); }
        while (g0 >= rb + (n - 1 - i)) { rb += (n - 1 - i); ++i; }
        int re = rb + (n - 1 - i);

        for (int st = 0; st < nst; ++st) {
            const int slot = st & (DEPTH - 1);
            mbar_wait(mba[slot], (st / DEPTH) & 1);

            const float* bs = &buf[slot][0];
            const int cb  = (s0 + st) * SLEN;
            const int lim = cb + SLEN;
            int pos = cb;

            if (re >= lim) {
                // fast path: whole stage inside row i (one segment)
                const float xi  = __ldg(x + i);
                const int joff = i + 1 - rb;
                float racc = 0.0f;
                #pragma unroll
                for (int k = 0; k < SLEN / TPB; ++k)
                    racc = fmaf(bs[k * TPB + t],
                                __ldg(x + cb + k * TPB + t + joff), racc);
                sum = fmaf(xi, racc, sum);
                pos = lim;
                if (pos == re) { rb = re; ++i; re += (n - 1 - i); }
            } else {
                // generic: walk row segments within this stage
                while (pos < lim) {
                    const int send = re < lim ? re : lim;
                    const float xi  = __ldg(x + i);
                    const int joff = i + 1 - rb;
                    float racc = 0.0f;
                    for (int g = pos + t; g < send; g += TPB)
                        racc = fmaf(bs[g - cb], __ldg(x + g + joff), racc);
                    sum = fmaf(xi, racc, sum);
                    pos = send;
                    if (pos == re) { rb = re; ++i; re += (n - 1 - i); }
                }
            }

            __syncthreads();   // all threads done with this slot's buffer
            if (t == 0 && st + DEPTH < nst) {
                const int nx = st + DEPTH;
                mbar_expect_tx(mba[slot], SLEN * 4);
                tma_1d((uint32_t)__cvta_generic_to_shared(&buf[slot][0]),
                       c2 + (long long)(s0 + nx) * SLEN, SLEN * 4, mba[slot]);
            }
        }
    }

    // tail for total % SLEN != 0 (none for n=8192; kept for generality)
    {
        const double nd = 2.0 * (double)n - 1.0;
        for (int g = nch * SLEN + b * TPB + t; g < total; g += G * TPB) {
            int i = (int)((nd - sqrt(nd * nd - 8.0 * (double)g)) * 0.5);
            if (i < 0) i = 0;
            if (i > n - 2) i = n - 2;
            int rb = (i * (2 * n - 1 - i)) >> 1;
            while (rb > g) { --i; rb -= (n - 1 - i); }
            while (g >= rb + (n - 1 - i)) { rb += (n - 1 - i); ++i; }
            const int j = g - rb + i + 1;
            sum = fmaf(__ldcs(c2 + g), __ldg(x + i) * __ldg(x + j), sum);
        }
    }

    // ---- block partial -> counter -> last block reduces + writes out ----
    float w = warp_sum(sum);
    if ((t & 31) == 0) wsum[t >> 5] = w;
    __syncthreads();
    if (t < 32) {
        float v = (t < TPB / 32) ? wsum[t] : 0.0f;
        v = warp_sum(v);
        if (t == 0) {
            g_parts[b] = v;
            __threadfence();
            unsigned int old = atomicInc(&g_ctr, (unsigned)(G - 1));
            lastflag = (old == (unsigned)(G - 1));
        }
    }
    __syncthreads();
    if (lastflag) {
        __threadfence();
        float v = 0.0f;
        for (int k = t; k < G; k += TPB) v += g_parts[k];
        float w2 = warp_sum(v);
        if ((t & 31) == 0) wsum[t >> 5] = w2;
        __syncthreads();
        if (t == 0) {
            float s2 = 0.0f;
            #pragma unroll
            for (int k = 0; k < TPB / 32; ++k) s2 += wsum[k];
            out[0] = s2;
        }
    }
}

extern "C" void kernel_launch(void* const* d_in, const int* in_sizes, int n_in,
                              void* d_out, int out_size) {
    const float* x = (const float*)d_in[0];
    const float* c = (const float*)d_in[1];
    float* out = (float*)d_out;
    const int n = in_sizes[0];   // 8192

    ham_kernel<<<NBLK, TPB>>>(x, c, out, n);
}